// round 3
// baseline (speedup 1.0000x reference)
#include <cuda_runtime.h>
#include <cuda_bf16.h>
#include <cstdint>

// ---------------------------------------------------------------------------
// ShufflerAttention fused pipeline (round 0: correctness + bf16 mma.sync)
//
// Shapes: B=4, NB=64, T=512, C=256, H=8, HD=32, FW=TW=8
// Windows: NWIN = 4*8*64 = 2048, each 64 tokens. MROWS = 131072 token-rows.
//
// Key identity: window token (b, n, t) gathers from and scatters to the SAME
// global position (b, perm_n[b,n], perm_t[b,t]).
// ---------------------------------------------------------------------------

#define NWIN  2048
#define MROWS 131072          // NWIN * 64
static constexpr float SCALE = 0.17677669529663689f;  // 32^-0.5

// Scratch (static device allocations are allowed; no cudaMalloc anywhere).
__device__ __align__(128) __nv_bfloat16 g_Xw [(size_t)MROWS * 256];  // LN'd, window-ordered
__device__ __align__(128) __nv_bfloat16 g_QKV[(size_t)MROWS * 768];  // [row][ q:0-255 | k:256-511 | v:512-767 ]
__device__ __align__(128) __nv_bfloat16 g_O  [(size_t)MROWS * 256];  // attention output
__device__ __align__(128) __nv_bfloat16 g_Wqkv[768 * 256];           // rows: Wq*SCALE | Wk | Wv   (row-major [n][k])
__device__ __align__(128) __nv_bfloat16 g_Wp  [256 * 256];

// ---------------------------------------------------------------------------
// mma.sync m16n8k16 bf16 (A row-major, B col-major i.e. stored [n][k])
// ---------------------------------------------------------------------------
__device__ __forceinline__ void mma_bf16(float c[4], const uint32_t a[4], const uint32_t b[2]) {
    asm volatile(
        "mma.sync.aligned.m16n8k16.row.col.f32.bf16.bf16.f32 "
        "{%0,%1,%2,%3}, {%4,%5,%6,%7}, {%8,%9}, {%0,%1,%2,%3};\n"
        : "+f"(c[0]), "+f"(c[1]), "+f"(c[2]), "+f"(c[3])
        : "r"(a[0]), "r"(a[1]), "r"(a[2]), "r"(a[3]), "r"(b[0]), "r"(b[1]));
}

__device__ __forceinline__ uint32_t pack_bf16(float lo, float hi) {
    __nv_bfloat162 t = __floats2bfloat162_rn(lo, hi);
    return *reinterpret_cast<uint32_t*>(&t);
}

// ---------------------------------------------------------------------------
// K0: weight convert to bf16 (fold SCALE into Wq rows)
// ---------------------------------------------------------------------------
__global__ void __launch_bounds__(256) k_wconv(const float* __restrict__ Wq,
                                               const float* __restrict__ Wk,
                                               const float* __restrict__ Wv,
                                               const float* __restrict__ Wp) {
    int j = blockIdx.x * 256 + threadIdx.x;      // 0..65535
    g_Wqkv[j]          = __float2bfloat16(Wq[j] * SCALE);
    g_Wqkv[65536 + j]  = __float2bfloat16(Wk[j]);
    g_Wqkv[131072 + j] = __float2bfloat16(Wv[j]);
    g_Wp[j]            = __float2bfloat16(Wp[j]);
}

// ---------------------------------------------------------------------------
// K1: LayerNorm + permuted gather into window order. 1 CTA per window.
// Warp handles 8 rows; lane handles 8 channels of each row.
// ---------------------------------------------------------------------------
__global__ void __launch_bounds__(256) k_ln_gather(const float* __restrict__ inpt,
                                                   const int*   __restrict__ perm_n,
                                                   const int*   __restrict__ perm_t,
                                                   const float* __restrict__ ln_g,
                                                   const float* __restrict__ ln_b) {
    const int w = blockIdx.x;
    const int bat = w >> 9, i = (w >> 6) & 7, j = w & 63;
    const int warp = threadIdx.x >> 5, lane = threadIdx.x & 31;
    const int c0 = lane * 8;

    float4 g0  = *(const float4*)(ln_g + c0);
    float4 g1  = *(const float4*)(ln_g + c0 + 4);
    float4 be0 = *(const float4*)(ln_b + c0);
    float4 be1 = *(const float4*)(ln_b + c0 + 4);

    for (int l = warp * 8; l < warp * 8 + 8; ++l) {
        const int fw = l >> 3, tw = l & 7;
        const int gn = __ldg(perm_n + bat * 64 + i * 8 + fw);
        const int gt = __ldg(perm_t + bat * 512 + j * 8 + tw);
        const float* src = inpt + ((size_t)((bat * 64 + gn) * 512 + gt)) * 256;
        float4 v0 = *(const float4*)(src + c0);
        float4 v1 = *(const float4*)(src + c0 + 4);
        float s  = v0.x + v0.y + v0.z + v0.w + v1.x + v1.y + v1.z + v1.w;
        float sq = v0.x*v0.x + v0.y*v0.y + v0.z*v0.z + v0.w*v0.w
                 + v1.x*v1.x + v1.y*v1.y + v1.z*v1.z + v1.w*v1.w;
        #pragma unroll
        for (int off = 16; off; off >>= 1) {
            s  += __shfl_xor_sync(0xffffffffu, s,  off);
            sq += __shfl_xor_sync(0xffffffffu, sq, off);
        }
        const float mean = s * (1.0f / 256.0f);
        const float var  = sq * (1.0f / 256.0f) - mean * mean;
        const float rinv = rsqrtf(var + 1e-5f);

        __nv_bfloat162* dst = (__nv_bfloat162*)(g_Xw + ((size_t)w * 64 + l) * 256 + c0);
        dst[0] = __floats2bfloat162_rn((v0.x - mean) * rinv * g0.x + be0.x,
                                       (v0.y - mean) * rinv * g0.y + be0.y);
        dst[1] = __floats2bfloat162_rn((v0.z - mean) * rinv * g0.z + be0.z,
                                       (v0.w - mean) * rinv * g0.w + be0.w);
        dst[2] = __floats2bfloat162_rn((v1.x - mean) * rinv * g1.x + be1.x,
                                       (v1.y - mean) * rinv * g1.y + be1.y);
        dst[3] = __floats2bfloat162_rn((v1.z - mean) * rinv * g1.z + be1.z,
                                       (v1.w - mean) * rinv * g1.w + be1.w);
    }
}

// ---------------------------------------------------------------------------
// K2: QKV GEMM. C[131072 x 768] = Xw @ Wqkv^T + bias.  CTA tile 128x128, K=256.
// 8 warps in a 2(m) x 4(n) grid; warp tile 64x32; 4x4 m16n8k16 tiles.
// smem rows padded to 72 bf16 (u32 stride 36 -> fragment banks 4g+q, conflict-free).
// ---------------------------------------------------------------------------
__device__ __forceinline__ float qkv_bias(int n, const float* bq, const float* bk, const float* bv) {
    if (n < 256) return __ldg(bq + n) * SCALE;
    if (n < 512) return __ldg(bk + n - 256);
    return __ldg(bv + n - 512);
}

__global__ void __launch_bounds__(256) k_qkv(const float* __restrict__ bq,
                                             const float* __restrict__ bk,
                                             const float* __restrict__ bv) {
    __shared__ __nv_bfloat16 As[128][72];
    __shared__ __nv_bfloat16 Bs[128][72];
    const int mBase = blockIdx.x * 128;
    const int nBase = blockIdx.y * 128;
    const int tid = threadIdx.x;
    const int warp = tid >> 5, lane = tid & 31;
    const int wm = warp & 1, wn = warp >> 1;
    const int g = lane >> 2, q = lane & 3;

    float acc[4][4][4];
    #pragma unroll
    for (int a = 0; a < 4; ++a)
        #pragma unroll
        for (int b = 0; b < 4; ++b)
            #pragma unroll
            for (int c = 0; c < 4; ++c) acc[a][b][c] = 0.f;

    for (int kc = 0; kc < 4; ++kc) {
        #pragma unroll
        for (int it = 0; it < 4; ++it) {
            const int lin = tid + it * 256;
            const int row = lin >> 3, c8 = (lin & 7) * 8;
            *(uint4*)(&As[row][c8]) =
                *(const uint4*)(g_Xw + (size_t)(mBase + row) * 256 + kc * 64 + c8);
            *(uint4*)(&Bs[row][c8]) =
                *(const uint4*)(g_Wqkv + (size_t)(nBase + row) * 256 + kc * 64 + c8);
        }
        __syncthreads();
        #pragma unroll
        for (int ks = 0; ks < 4; ++ks) {
            const int kk = ks * 16 + q * 2;
            uint32_t afr[4][4], bfr[4][2];
            #pragma unroll
            for (int mi = 0; mi < 4; ++mi) {
                const int r = wm * 64 + mi * 16 + g;
                afr[mi][0] = *(const uint32_t*)&As[r][kk];
                afr[mi][1] = *(const uint32_t*)&As[r + 8][kk];
                afr[mi][2] = *(const uint32_t*)&As[r][kk + 8];
                afr[mi][3] = *(const uint32_t*)&As[r + 8][kk + 8];
            }
            #pragma unroll
            for (int ni = 0; ni < 4; ++ni) {
                const int n = wn * 32 + ni * 8 + g;
                bfr[ni][0] = *(const uint32_t*)&Bs[n][kk];
                bfr[ni][1] = *(const uint32_t*)&Bs[n][kk + 8];
            }
            #pragma unroll
            for (int mi = 0; mi < 4; ++mi)
                #pragma unroll
                for (int ni = 0; ni < 4; ++ni)
                    mma_bf16(acc[mi][ni], afr[mi], bfr[ni]);
        }
        __syncthreads();
    }

    #pragma unroll
    for (int mi = 0; mi < 4; ++mi) {
        const int r0 = mBase + wm * 64 + mi * 16 + g;
        #pragma unroll
        for (int ni = 0; ni < 4; ++ni) {
            const int n0 = nBase + wn * 32 + ni * 8 + q * 2;
            const float b0 = qkv_bias(n0, bq, bk, bv);
            const float b1 = qkv_bias(n0 + 1, bq, bk, bv);
            *(__nv_bfloat162*)(g_QKV + (size_t)r0 * 768 + n0) =
                __floats2bfloat162_rn(acc[mi][ni][0] + b0, acc[mi][ni][1] + b1);
            *(__nv_bfloat162*)(g_QKV + (size_t)(r0 + 8) * 768 + n0) =
                __floats2bfloat162_rn(acc[mi][ni][2] + b0, acc[mi][ni][3] + b1);
        }
    }
}

// ---------------------------------------------------------------------------
// K3: attention per (window, head). 128 threads; warp = 16 query rows.
// S = Q K^T (k=32), softmax over 64, O = P V (k=64, P stays in registers:
// c-frag pairs of S are exactly the a-frag of the PV mma).
// ---------------------------------------------------------------------------
__global__ void __launch_bounds__(128) k_attn() {
    __shared__ __nv_bfloat16 Qs[64][40];
    __shared__ __nv_bfloat16 Ks[64][40];
    __shared__ __nv_bfloat16 Vt[32][72];   // [dim][token]
    const int w = blockIdx.x >> 3, h = blockIdx.x & 7;
    const int tid = threadIdx.x;
    const int warp = tid >> 5, lane = tid & 31;

    const __nv_bfloat16* base = g_QKV + (size_t)w * 64 * 768 + h * 32;
    {
        const int r = tid >> 1;
        const int half = (tid & 1) * 16;
        const __nv_bfloat16* qrow = base + (size_t)r * 768 + half;
        *(uint4*)&Qs[r][half]     = *(const uint4*)(qrow);
        *(uint4*)&Qs[r][half + 8] = *(const uint4*)(qrow + 8);
        *(uint4*)&Ks[r][half]     = *(const uint4*)(qrow + 256);
        *(uint4*)&Ks[r][half + 8] = *(const uint4*)(qrow + 256 + 8);
        __nv_bfloat16 tmp[16];
        *(uint4*)(tmp)     = *(const uint4*)(qrow + 512);
        *(uint4*)(tmp + 8) = *(const uint4*)(qrow + 512 + 8);
        #pragma unroll
        for (int d = 0; d < 16; ++d) Vt[half + d][r] = tmp[d];
    }
    __syncthreads();

    const int g = lane >> 2, q = lane & 3;
    const int m0 = warp * 16;

    float s[8][4];
    #pragma unroll
    for (int ni = 0; ni < 8; ++ni) { s[ni][0] = s[ni][1] = s[ni][2] = s[ni][3] = 0.f; }

    #pragma unroll
    for (int ks = 0; ks < 2; ++ks) {
        const int kk = ks * 16 + q * 2;
        uint32_t a[4];
        a[0] = *(const uint32_t*)&Qs[m0 + g][kk];
        a[1] = *(const uint32_t*)&Qs[m0 + g + 8][kk];
        a[2] = *(const uint32_t*)&Qs[m0 + g][kk + 8];
        a[3] = *(const uint32_t*)&Qs[m0 + g + 8][kk + 8];
        #pragma unroll
        for (int ni = 0; ni < 8; ++ni) {
            uint32_t bb[2];
            bb[0] = *(const uint32_t*)&Ks[ni * 8 + g][kk];
            bb[1] = *(const uint32_t*)&Ks[ni * 8 + g][kk + 8];
            mma_bf16(s[ni], a, bb);
        }
    }

    // softmax over 64 cols; row (m0+g) -> s[*][0..1], row (m0+g+8) -> s[*][2..3]
    float mx0 = -1e30f, mx1 = -1e30f;
    #pragma unroll
    for (int ni = 0; ni < 8; ++ni) {
        mx0 = fmaxf(mx0, fmaxf(s[ni][0], s[ni][1]));
        mx1 = fmaxf(mx1, fmaxf(s[ni][2], s[ni][3]));
    }
    mx0 = fmaxf(mx0, __shfl_xor_sync(0xffffffffu, mx0, 1));
    mx0 = fmaxf(mx0, __shfl_xor_sync(0xffffffffu, mx0, 2));
    mx1 = fmaxf(mx1, __shfl_xor_sync(0xffffffffu, mx1, 1));
    mx1 = fmaxf(mx1, __shfl_xor_sync(0xffffffffu, mx1, 2));
    float sum0 = 0.f, sum1 = 0.f;
    #pragma unroll
    for (int ni = 0; ni < 8; ++ni) {
        s[ni][0] = __expf(s[ni][0] - mx0);
        s[ni][1] = __expf(s[ni][1] - mx0);
        s[ni][2] = __expf(s[ni][2] - mx1);
        s[ni][3] = __expf(s[ni][3] - mx1);
        sum0 += s[ni][0] + s[ni][1];
        sum1 += s[ni][2] + s[ni][3];
    }
    sum0 += __shfl_xor_sync(0xffffffffu, sum0, 1);
    sum0 += __shfl_xor_sync(0xffffffffu, sum0, 2);
    sum1 += __shfl_xor_sync(0xffffffffu, sum1, 1);
    sum1 += __shfl_xor_sync(0xffffffffu, sum1, 2);
    const float inv0 = 1.f / sum0, inv1 = 1.f / sum1;

    float o[4][4];
    #pragma unroll
    for (int ni = 0; ni < 4; ++ni) { o[ni][0] = o[ni][1] = o[ni][2] = o[ni][3] = 0.f; }

    #pragma unroll
    for (int kt = 0; kt < 4; ++kt) {
        uint32_t a[4];
        a[0] = pack_bf16(s[2 * kt][0],     s[2 * kt][1]);
        a[1] = pack_bf16(s[2 * kt][2],     s[2 * kt][3]);
        a[2] = pack_bf16(s[2 * kt + 1][0], s[2 * kt + 1][1]);
        a[3] = pack_bf16(s[2 * kt + 1][2], s[2 * kt + 1][3]);
        const int t0 = kt * 16 + q * 2;
        #pragma unroll
        for (int ni = 0; ni < 4; ++ni) {
            uint32_t bb[2];
            bb[0] = *(const uint32_t*)&Vt[ni * 8 + g][t0];
            bb[1] = *(const uint32_t*)&Vt[ni * 8 + g][t0 + 8];
            mma_bf16(o[ni], a, bb);
        }
    }

    #pragma unroll
    for (int ni = 0; ni < 4; ++ni) {
        const int d0 = h * 32 + ni * 8 + q * 2;
        const size_t row0 = (size_t)w * 64 + m0 + g;
        *(__nv_bfloat162*)(g_O + row0 * 256 + d0) =
            __floats2bfloat162_rn(o[ni][0] * inv0, o[ni][1] * inv0);
        *(__nv_bfloat162*)(g_O + (row0 + 8) * 256 + d0) =
            __floats2bfloat162_rn(o[ni][2] * inv1, o[ni][3] * inv1);
    }
}

// ---------------------------------------------------------------------------
// K4: output projection + bias + residual + inverse-permutation scatter.
// Same GEMM structure as K2 (N=256). Scatter target == original gather source.
// ---------------------------------------------------------------------------
__global__ void __launch_bounds__(256) k_proj(const float* __restrict__ inpt,
                                              const int*   __restrict__ perm_n,
                                              const int*   __restrict__ perm_t,
                                              const float* __restrict__ bp,
                                              float* __restrict__ out) {
    __shared__ __nv_bfloat16 As[128][72];
    __shared__ __nv_bfloat16 Bs[128][72];
    const int mBase = blockIdx.x * 128;
    const int nBase = blockIdx.y * 128;
    const int tid = threadIdx.x;
    const int warp = tid >> 5, lane = tid & 31;
    const int wm = warp & 1, wn = warp >> 1;
    const int g = lane >> 2, q = lane & 3;

    float acc[4][4][4];
    #pragma unroll
    for (int a = 0; a < 4; ++a)
        #pragma unroll
        for (int b = 0; b < 4; ++b)
            #pragma unroll
            for (int c = 0; c < 4; ++c) acc[a][b][c] = 0.f;

    for (int kc = 0; kc < 4; ++kc) {
        #pragma unroll
        for (int it = 0; it < 4; ++it) {
            const int lin = tid + it * 256;
            const int row = lin >> 3, c8 = (lin & 7) * 8;
            *(uint4*)(&As[row][c8]) =
                *(const uint4*)(g_O + (size_t)(mBase + row) * 256 + kc * 64 + c8);
            *(uint4*)(&Bs[row][c8]) =
                *(const uint4*)(g_Wp + (size_t)(nBase + row) * 256 + kc * 64 + c8);
        }
        __syncthreads();
        #pragma unroll
        for (int ks = 0; ks < 4; ++ks) {
            const int kk = ks * 16 + q * 2;
            uint32_t afr[4][4], bfr[4][2];
            #pragma unroll
            for (int mi = 0; mi < 4; ++mi) {
                const int r = wm * 64 + mi * 16 + g;
                afr[mi][0] = *(const uint32_t*)&As[r][kk];
                afr[mi][1] = *(const uint32_t*)&As[r + 8][kk];
                afr[mi][2] = *(const uint32_t*)&As[r][kk + 8];
                afr[mi][3] = *(const uint32_t*)&As[r + 8][kk + 8];
            }
            #pragma unroll
            for (int ni = 0; ni < 4; ++ni) {
                const int n = wn * 32 + ni * 8 + g;
                bfr[ni][0] = *(const uint32_t*)&Bs[n][kk];
                bfr[ni][1] = *(const uint32_t*)&Bs[n][kk + 8];
            }
            #pragma unroll
            for (int mi = 0; mi < 4; ++mi)
                #pragma unroll
                for (int ni = 0; ni < 4; ++ni)
                    mma_bf16(acc[mi][ni], afr[mi], bfr[ni]);
        }
        __syncthreads();
    }

    #pragma unroll
    for (int mi = 0; mi < 4; ++mi) {
        size_t gbase[2];
        #pragma unroll
        for (int t = 0; t < 2; ++t) {
            const int r = mBase + wm * 64 + mi * 16 + g + t * 8;
            const int w = r >> 6, l = r & 63;
            const int bat = w >> 9, i = (w >> 6) & 7, j = w & 63;
            const int fw = l >> 3, tw = l & 7;
            const int gn = __ldg(perm_n + bat * 64 + i * 8 + fw);
            const int gt = __ldg(perm_t + bat * 512 + j * 8 + tw);
            gbase[t] = (size_t)((bat * 64 + gn) * 512 + gt) * 256;
        }
        #pragma unroll
        for (int ni = 0; ni < 4; ++ni) {
            const int n0 = nBase + wn * 32 + ni * 8 + q * 2;
            const float bp0 = __ldg(bp + n0), bp1 = __ldg(bp + n0 + 1);
            float2 r0v = *(const float2*)(inpt + gbase[0] + n0);
            float2 r1v = *(const float2*)(inpt + gbase[1] + n0);
            *(float2*)(out + gbase[0] + n0) =
                make_float2(r0v.x + acc[mi][ni][0] + bp0, r0v.y + acc[mi][ni][1] + bp1);
            *(float2*)(out + gbase[1] + n0) =
                make_float2(r1v.x + acc[mi][ni][2] + bp0, r1v.y + acc[mi][ni][3] + bp1);
        }
    }
}

// ---------------------------------------------------------------------------
// Launch
// ---------------------------------------------------------------------------
extern "C" void kernel_launch(void* const* d_in, const int* in_sizes, int n_in,
                              void* d_out, int out_size) {
    const float* inpt   = (const float*)d_in[0];
    const int*   perm_n = (const int*)  d_in[1];
    const int*   perm_t = (const int*)  d_in[2];
    const float* ln_g   = (const float*)d_in[3];
    const float* ln_b   = (const float*)d_in[4];
    const float* Wq     = (const float*)d_in[5];
    const float* bq     = (const float*)d_in[6];
    const float* Wk     = (const float*)d_in[7];
    const float* bk     = (const float*)d_in[8];
    const float* Wv     = (const float*)d_in[9];
    const float* bv     = (const float*)d_in[10];
    const float* Wp     = (const float*)d_in[11];
    const float* bp     = (const float*)d_in[12];
    float* out = (float*)d_out;

    k_wconv<<<256, 256>>>(Wq, Wk, Wv, Wp);
    k_ln_gather<<<NWIN, 256>>>(inpt, perm_n, perm_t, ln_g, ln_b);
    k_qkv<<<dim3(1024, 6), 256>>>(bq, bk, bv);
    k_attn<<<NWIN * 8, 128>>>();
    k_proj<<<dim3(1024, 2), 256>>>(inpt, perm_n, perm_t, bp, out);
}

// round 4
// speedup vs baseline: 1.2619x; 1.2619x over previous
#include <cuda_runtime.h>
#include <cuda_bf16.h>
#include <cstdint>

// ---------------------------------------------------------------------------
// ShufflerAttention fused pipeline (round 4: cp.async pipelines + ldmatrix)
// Shapes: B=4, NB=64, T=512, C=256, H=8, HD=32, FW=TW=8
// NWIN = 2048 windows x 64 tokens. MROWS = 131072 token-rows.
// Window token (b,n,t) gathers from and scatters to the SAME global position.
// ---------------------------------------------------------------------------

#define NWIN  2048
#define MROWS 131072
static constexpr float SCALE = 0.17677669529663689f;  // 32^-0.5

__device__ __align__(128) __nv_bfloat16 g_Xw [(size_t)MROWS * 256];
__device__ __align__(128) __nv_bfloat16 g_QKV[(size_t)MROWS * 768];
__device__ __align__(128) __nv_bfloat16 g_O  [(size_t)MROWS * 256];
__device__ __align__(128) __nv_bfloat16 g_Wqkv[768 * 256];
__device__ __align__(128) __nv_bfloat16 g_Wp  [256 * 256];

// ----------------------------- PTX helpers --------------------------------
__device__ __forceinline__ void mma_bf16(float c[4], const uint32_t a[4], const uint32_t b[2]) {
    asm volatile(
        "mma.sync.aligned.m16n8k16.row.col.f32.bf16.bf16.f32 "
        "{%0,%1,%2,%3}, {%4,%5,%6,%7}, {%8,%9}, {%0,%1,%2,%3};\n"
        : "+f"(c[0]), "+f"(c[1]), "+f"(c[2]), "+f"(c[3])
        : "r"(a[0]), "r"(a[1]), "r"(a[2]), "r"(a[3]), "r"(b[0]), "r"(b[1]));
}
__device__ __forceinline__ uint32_t pack_bf16(float lo, float hi) {
    __nv_bfloat162 t = __floats2bfloat162_rn(lo, hi);
    return *reinterpret_cast<uint32_t*>(&t);
}
__device__ __forceinline__ uint32_t smem_u32(const void* p) {
    return (uint32_t)__cvta_generic_to_shared(p);
}
__device__ __forceinline__ void cp_async16(uint32_t dst, const void* src) {
    asm volatile("cp.async.cg.shared.global [%0], [%1], 16;\n" :: "r"(dst), "l"(src));
}
__device__ __forceinline__ void cp_commit() { asm volatile("cp.async.commit_group;\n"); }
__device__ __forceinline__ void cp_wait0() { asm volatile("cp.async.wait_group 0;\n"); }
__device__ __forceinline__ void cp_wait1() { asm volatile("cp.async.wait_group 1;\n"); }
__device__ __forceinline__ void ldmx4(uint32_t& r0, uint32_t& r1, uint32_t& r2, uint32_t& r3,
                                      uint32_t addr) {
    asm volatile("ldmatrix.sync.aligned.m8n8.x4.shared.b16 {%0,%1,%2,%3}, [%4];\n"
                 : "=r"(r0), "=r"(r1), "=r"(r2), "=r"(r3) : "r"(addr));
}
__device__ __forceinline__ void ldmx4t(uint32_t& r0, uint32_t& r1, uint32_t& r2, uint32_t& r3,
                                       uint32_t addr) {
    asm volatile("ldmatrix.sync.aligned.m8n8.x4.trans.shared.b16 {%0,%1,%2,%3}, [%4];\n"
                 : "=r"(r0), "=r"(r1), "=r"(r2), "=r"(r3) : "r"(addr));
}

// ---------------------------------------------------------------------------
// K0: weight convert to bf16 (fold SCALE into Wq rows)
// ---------------------------------------------------------------------------
__global__ void __launch_bounds__(256) k_wconv(const float* __restrict__ Wq,
                                               const float* __restrict__ Wk,
                                               const float* __restrict__ Wv,
                                               const float* __restrict__ Wp) {
    int j = blockIdx.x * 256 + threadIdx.x;
    g_Wqkv[j]          = __float2bfloat16(Wq[j] * SCALE);
    g_Wqkv[65536 + j]  = __float2bfloat16(Wk[j]);
    g_Wqkv[131072 + j] = __float2bfloat16(Wv[j]);
    g_Wp[j]            = __float2bfloat16(Wp[j]);
}

// ---------------------------------------------------------------------------
// K1: LayerNorm + permuted gather into window order. 1 CTA per window.
// ---------------------------------------------------------------------------
__global__ void __launch_bounds__(256) k_ln_gather(const float* __restrict__ inpt,
                                                   const int*   __restrict__ perm_n,
                                                   const int*   __restrict__ perm_t,
                                                   const float* __restrict__ ln_g,
                                                   const float* __restrict__ ln_b) {
    const int w = blockIdx.x;
    const int bat = w >> 9, i = (w >> 6) & 7, j = w & 63;
    const int warp = threadIdx.x >> 5, lane = threadIdx.x & 31;
    const int c0 = lane * 8;

    float4 g0  = *(const float4*)(ln_g + c0);
    float4 g1  = *(const float4*)(ln_g + c0 + 4);
    float4 be0 = *(const float4*)(ln_b + c0);
    float4 be1 = *(const float4*)(ln_b + c0 + 4);

    for (int l = warp * 8; l < warp * 8 + 8; ++l) {
        const int fw = l >> 3, tw = l & 7;
        const int gn = __ldg(perm_n + bat * 64 + i * 8 + fw);
        const int gt = __ldg(perm_t + bat * 512 + j * 8 + tw);
        const float* src = inpt + ((size_t)((bat * 64 + gn) * 512 + gt)) * 256;
        float4 v0 = *(const float4*)(src + c0);
        float4 v1 = *(const float4*)(src + c0 + 4);
        float s  = v0.x + v0.y + v0.z + v0.w + v1.x + v1.y + v1.z + v1.w;
        float sq = v0.x*v0.x + v0.y*v0.y + v0.z*v0.z + v0.w*v0.w
                 + v1.x*v1.x + v1.y*v1.y + v1.z*v1.z + v1.w*v1.w;
        #pragma unroll
        for (int off = 16; off; off >>= 1) {
            s  += __shfl_xor_sync(0xffffffffu, s,  off);
            sq += __shfl_xor_sync(0xffffffffu, sq, off);
        }
        const float mean = s * (1.0f / 256.0f);
        const float var  = sq * (1.0f / 256.0f) - mean * mean;
        const float rinv = rsqrtf(var + 1e-5f);

        __nv_bfloat162* dst = (__nv_bfloat162*)(g_Xw + ((size_t)w * 64 + l) * 256 + c0);
        dst[0] = __floats2bfloat162_rn((v0.x - mean) * rinv * g0.x + be0.x,
                                       (v0.y - mean) * rinv * g0.y + be0.y);
        dst[1] = __floats2bfloat162_rn((v0.z - mean) * rinv * g0.z + be0.z,
                                       (v0.w - mean) * rinv * g0.w + be0.w);
        dst[2] = __floats2bfloat162_rn((v1.x - mean) * rinv * g1.x + be1.x,
                                       (v1.y - mean) * rinv * g1.y + be1.y);
        dst[3] = __floats2bfloat162_rn((v1.z - mean) * rinv * g1.z + be1.z,
                                       (v1.w - mean) * rinv * g1.w + be1.w);
    }
}

// ---------------------------------------------------------------------------
// GEMM core: 128x128 CTA tile, K streamed in 32-wide slabs, 2-stage cp.async
// pipeline, ldmatrix fragment loads. 8 warps = 2(m) x 4(n), warp tile 64x32.
// smem row stride 40 bf16 = 80B -> 8-row ldmatrix phases hit distinct banks.
// ---------------------------------------------------------------------------
struct GemmFrag {
    float acc[4][4][4];
};

__device__ __forceinline__ void gemm_mainloop(const __nv_bfloat16* __restrict__ Aglob,
                                              const __nv_bfloat16* __restrict__ Bglob,
                                              int mBase, int nBase,
                                              __nv_bfloat16 (*As)[128][40],
                                              __nv_bfloat16 (*Bs)[128][40],
                                              float acc[4][4][4]) {
    const int tid = threadIdx.x;
    const int warp = tid >> 5, lane = tid & 31;
    const int wm = warp & 1, wn = warp >> 1;

    #pragma unroll
    for (int a = 0; a < 4; ++a)
        #pragma unroll
        for (int b = 0; b < 4; ++b)
            #pragma unroll
            for (int c = 0; c < 4; ++c) acc[a][b][c] = 0.f;

    // per-thread load map: 128 rows x 32 cols = 512 x 16B chunks; 256 thr x 2
    const int lrow0 = tid >> 2, lc8 = (tid & 3) * 8;     // +64 rows on 2nd iter

    // ldmatrix addresses (per warp)
    const int aRow = wm * 64 + (lane & 15);
    const int aCol = (lane >> 4) * 8;
    const int bRow = wn * 32 + ((lane >> 4) << 3) + (lane & 7);
    const int bCol = ((lane >> 3) & 1) * 8;

    // prologue: stage 0
    #pragma unroll
    for (int it = 0; it < 2; ++it) {
        const int row = lrow0 + it * 64;
        cp_async16(smem_u32(&As[0][row][lc8]), Aglob + (size_t)(mBase + row) * 256 + lc8);
        cp_async16(smem_u32(&Bs[0][row][lc8]), Bglob + (size_t)(nBase + row) * 256 + lc8);
    }
    cp_commit();

    for (int kc = 0; kc < 8; ++kc) {
        const int buf = kc & 1;
        if (kc < 7) {
            const int nb = buf ^ 1;
            #pragma unroll
            for (int it = 0; it < 2; ++it) {
                const int row = lrow0 + it * 64;
                cp_async16(smem_u32(&As[nb][row][lc8]),
                           Aglob + (size_t)(mBase + row) * 256 + (kc + 1) * 32 + lc8);
                cp_async16(smem_u32(&Bs[nb][row][lc8]),
                           Bglob + (size_t)(nBase + row) * 256 + (kc + 1) * 32 + lc8);
            }
            cp_commit();
            cp_wait1();
        } else {
            cp_wait0();
        }
        __syncthreads();

        #pragma unroll
        for (int ks = 0; ks < 2; ++ks) {
            const int k0 = ks * 16;
            uint32_t afr[4][4], bfr[4][2];
            #pragma unroll
            for (int mi = 0; mi < 4; ++mi)
                ldmx4(afr[mi][0], afr[mi][1], afr[mi][2], afr[mi][3],
                      smem_u32(&As[buf][aRow + mi * 16][k0 + aCol]));
            #pragma unroll
            for (int nip = 0; nip < 2; ++nip)
                ldmx4(bfr[2 * nip][0], bfr[2 * nip][1], bfr[2 * nip + 1][0], bfr[2 * nip + 1][1],
                      smem_u32(&Bs[buf][bRow + nip * 16][k0 + bCol]));
            #pragma unroll
            for (int mi = 0; mi < 4; ++mi)
                #pragma unroll
                for (int ni = 0; ni < 4; ++ni)
                    mma_bf16(acc[mi][ni], afr[mi], bfr[ni]);
        }
        __syncthreads();
    }
}

// ---------------------------------------------------------------------------
// K2: QKV GEMM. grid (6 n-blocks fastest, 1024 m-blocks) -> A tiles L2-shared.
// ---------------------------------------------------------------------------
__device__ __forceinline__ float qkv_bias(int n, const float* bq, const float* bk, const float* bv) {
    if (n < 256) return __ldg(bq + n) * SCALE;
    if (n < 512) return __ldg(bk + n - 256);
    return __ldg(bv + n - 512);
}

__global__ void __launch_bounds__(256) k_qkv(const float* __restrict__ bq,
                                             const float* __restrict__ bk,
                                             const float* __restrict__ bv) {
    __shared__ __nv_bfloat16 As[2][128][40];
    __shared__ __nv_bfloat16 Bs[2][128][40];
    const int nBase = blockIdx.x * 128;     // fastest dim -> L2 reuse of A
    const int mBase = blockIdx.y * 128;
    const int warp = threadIdx.x >> 5, lane = threadIdx.x & 31;
    const int wm = warp & 1, wn = warp >> 1;
    const int g = lane >> 2, q = lane & 3;

    float acc[4][4][4];
    gemm_mainloop(g_Xw, g_Wqkv, mBase, nBase, As, Bs, acc);

    #pragma unroll
    for (int mi = 0; mi < 4; ++mi) {
        const int r0 = mBase + wm * 64 + mi * 16 + g;
        #pragma unroll
        for (int ni = 0; ni < 4; ++ni) {
            const int n0 = nBase + wn * 32 + ni * 8 + q * 2;
            const float b0 = qkv_bias(n0, bq, bk, bv);
            const float b1 = qkv_bias(n0 + 1, bq, bk, bv);
            *(__nv_bfloat162*)(g_QKV + (size_t)r0 * 768 + n0) =
                __floats2bfloat162_rn(acc[mi][ni][0] + b0, acc[mi][ni][1] + b1);
            *(__nv_bfloat162*)(g_QKV + (size_t)(r0 + 8) * 768 + n0) =
                __floats2bfloat162_rn(acc[mi][ni][2] + b0, acc[mi][ni][3] + b1);
        }
    }
}

// ---------------------------------------------------------------------------
// K3: attention per (window, head). V stored naturally; ldmatrix(.trans)
// produces all fragments. P stays in registers between the two MMAs.
// ---------------------------------------------------------------------------
__global__ void __launch_bounds__(128) k_attn() {
    __shared__ __nv_bfloat16 Qs[64][40];
    __shared__ __nv_bfloat16 Ks[64][40];
    __shared__ __nv_bfloat16 Vs[64][40];   // [token][dim]
    const int w = blockIdx.x >> 3, h = blockIdx.x & 7;
    const int tid = threadIdx.x;
    const int warp = tid >> 5, lane = tid & 31;

    {
        const int r = tid >> 1;
        const int half = (tid & 1) * 16;
        const __nv_bfloat16* qrow = g_QKV + (size_t)w * 64 * 768 + (size_t)r * 768 + h * 32 + half;
        cp_async16(smem_u32(&Qs[r][half]),     qrow);
        cp_async16(smem_u32(&Qs[r][half + 8]), qrow + 8);
        cp_async16(smem_u32(&Ks[r][half]),     qrow + 256);
        cp_async16(smem_u32(&Ks[r][half + 8]), qrow + 256 + 8);
        cp_async16(smem_u32(&Vs[r][half]),     qrow + 512);
        cp_async16(smem_u32(&Vs[r][half + 8]), qrow + 512 + 8);
        cp_commit();
    }
    cp_wait0();
    __syncthreads();

    const int g = lane >> 2, q = lane & 3;
    const int m0 = warp * 16;
    const int frRow = lane & 15;            // ldmatrix row-within-16
    const int frCol = (lane >> 4) * 8;      // ldmatrix col group
    const int bRow = ((lane >> 4) << 3) + (lane & 7);
    const int bCol = ((lane >> 3) & 1) * 8;

    float s[8][4];
    #pragma unroll
    for (int ni = 0; ni < 8; ++ni) { s[ni][0] = s[ni][1] = s[ni][2] = s[ni][3] = 0.f; }

    #pragma unroll
    for (int ks = 0; ks < 2; ++ks) {
        const int k0 = ks * 16;
        uint32_t a[4];
        ldmx4(a[0], a[1], a[2], a[3], smem_u32(&Qs[m0 + frRow][k0 + frCol]));
        #pragma unroll
        for (int nip = 0; nip < 4; ++nip) {
            uint32_t bb[4];
            ldmx4(bb[0], bb[1], bb[2], bb[3], smem_u32(&Ks[nip * 16 + bRow][k0 + bCol]));
            mma_bf16(s[2 * nip],     a, bb);
            mma_bf16(s[2 * nip + 1], a, bb + 2);
        }
    }

    // softmax over 64 cols; row (m0+g) -> s[*][0..1], row (m0+g+8) -> s[*][2..3]
    float mx0 = -1e30f, mx1 = -1e30f;
    #pragma unroll
    for (int ni = 0; ni < 8; ++ni) {
        mx0 = fmaxf(mx0, fmaxf(s[ni][0], s[ni][1]));
        mx1 = fmaxf(mx1, fmaxf(s[ni][2], s[ni][3]));
    }
    mx0 = fmaxf(mx0, __shfl_xor_sync(0xffffffffu, mx0, 1));
    mx0 = fmaxf(mx0, __shfl_xor_sync(0xffffffffu, mx0, 2));
    mx1 = fmaxf(mx1, __shfl_xor_sync(0xffffffffu, mx1, 1));
    mx1 = fmaxf(mx1, __shfl_xor_sync(0xffffffffu, mx1, 2));
    float sum0 = 0.f, sum1 = 0.f;
    #pragma unroll
    for (int ni = 0; ni < 8; ++ni) {
        s[ni][0] = __expf(s[ni][0] - mx0);
        s[ni][1] = __expf(s[ni][1] - mx0);
        s[ni][2] = __expf(s[ni][2] - mx1);
        s[ni][3] = __expf(s[ni][3] - mx1);
        sum0 += s[ni][0] + s[ni][1];
        sum1 += s[ni][2] + s[ni][3];
    }
    sum0 += __shfl_xor_sync(0xffffffffu, sum0, 1);
    sum0 += __shfl_xor_sync(0xffffffffu, sum0, 2);
    sum1 += __shfl_xor_sync(0xffffffffu, sum1, 1);
    sum1 += __shfl_xor_sync(0xffffffffu, sum1, 2);
    const float inv0 = 1.f / sum0, inv1 = 1.f / sum1;

    float o[4][4];
    #pragma unroll
    for (int ni = 0; ni < 4; ++ni) { o[ni][0] = o[ni][1] = o[ni][2] = o[ni][3] = 0.f; }

    #pragma unroll
    for (int kt = 0; kt < 4; ++kt) {
        uint32_t a[4];
        a[0] = pack_bf16(s[2 * kt][0],     s[2 * kt][1]);
        a[1] = pack_bf16(s[2 * kt][2],     s[2 * kt][3]);
        a[2] = pack_bf16(s[2 * kt + 1][0], s[2 * kt + 1][1]);
        a[3] = pack_bf16(s[2 * kt + 1][2], s[2 * kt + 1][3]);
        const int t0 = kt * 16;
        #pragma unroll
        for (int nip = 0; nip < 2; ++nip) {
            uint32_t bb[4];
            // trans-ldmatrix on [token][dim] storage = V^T fragment
            ldmx4t(bb[0], bb[1], bb[2], bb[3],
                   smem_u32(&Vs[t0 + frRow][nip * 16 + frCol]));
            mma_bf16(o[2 * nip],     a, bb);
            mma_bf16(o[2 * nip + 1], a, bb + 2);
        }
    }

    #pragma unroll
    for (int ni = 0; ni < 4; ++ni) {
        const int d0 = h * 32 + ni * 8 + q * 2;
        const size_t row0 = (size_t)w * 64 + m0 + g;
        *(__nv_bfloat162*)(g_O + row0 * 256 + d0) =
            __floats2bfloat162_rn(o[ni][0] * inv0, o[ni][1] * inv0);
        *(__nv_bfloat162*)(g_O + (row0 + 8) * 256 + d0) =
            __floats2bfloat162_rn(o[ni][2] * inv1, o[ni][3] * inv1);
    }
}

// ---------------------------------------------------------------------------
// K4: output projection + bias + residual + inverse-permutation scatter.
// grid (2 n-blocks fastest, 1024 m-blocks).
// ---------------------------------------------------------------------------
__global__ void __launch_bounds__(256) k_proj(const float* __restrict__ inpt,
                                              const int*   __restrict__ perm_n,
                                              const int*   __restrict__ perm_t,
                                              const float* __restrict__ bp,
                                              float* __restrict__ out) {
    __shared__ __nv_bfloat16 As[2][128][40];
    __shared__ __nv_bfloat16 Bs[2][128][40];
    const int nBase = blockIdx.x * 128;
    const int mBase = blockIdx.y * 128;
    const int warp = threadIdx.x >> 5, lane = threadIdx.x & 31;
    const int wm = warp & 1, wn = warp >> 1;
    const int g = lane >> 2, q = lane & 3;

    float acc[4][4][4];
    gemm_mainloop(g_O, g_Wp, mBase, nBase, As, Bs, acc);

    #pragma unroll
    for (int mi = 0; mi < 4; ++mi) {
        size_t gbase[2];
        #pragma unroll
        for (int t = 0; t < 2; ++t) {
            const int r = mBase + wm * 64 + mi * 16 + g + t * 8;
            const int w = r >> 6, l = r & 63;
            const int bat = w >> 9, i = (w >> 6) & 7, j = w & 63;
            const int fw = l >> 3, tw = l & 7;
            const int gn = __ldg(perm_n + bat * 64 + i * 8 + fw);
            const int gt = __ldg(perm_t + bat * 512 + j * 8 + tw);
            gbase[t] = (size_t)((bat * 64 + gn) * 512 + gt) * 256;
        }
        #pragma unroll
        for (int ni = 0; ni < 4; ++ni) {
            const int n0 = nBase + wn * 32 + ni * 8 + q * 2;
            const float bp0 = __ldg(bp + n0), bp1 = __ldg(bp + n0 + 1);
            float2 r0v = *(const float2*)(inpt + gbase[0] + n0);
            float2 r1v = *(const float2*)(inpt + gbase[1] + n0);
            *(float2*)(out + gbase[0] + n0) =
                make_float2(r0v.x + acc[mi][ni][0] + bp0, r0v.y + acc[mi][ni][1] + bp1);
            *(float2*)(out + gbase[1] + n0) =
                make_float2(r1v.x + acc[mi][ni][2] + bp0, r1v.y + acc[mi][ni][3] + bp1);
        }
    }
}

// ---------------------------------------------------------------------------
// Launch
// ---------------------------------------------------------------------------
extern "C" void kernel_launch(void* const* d_in, const int* in_sizes, int n_in,
                              void* d_out, int out_size) {
    const float* inpt   = (const float*)d_in[0];
    const int*   perm_n = (const int*)  d_in[1];
    const int*   perm_t = (const int*)  d_in[2];
    const float* ln_g   = (const float*)d_in[3];
    const float* ln_b   = (const float*)d_in[4];
    const float* Wq     = (const float*)d_in[5];
    const float* bq     = (const float*)d_in[6];
    const float* Wk     = (const float*)d_in[7];
    const float* bk     = (const float*)d_in[8];
    const float* Wv     = (const float*)d_in[9];
    const float* bv     = (const float*)d_in[10];
    const float* Wp     = (const float*)d_in[11];
    const float* bp     = (const float*)d_in[12];
    float* out = (float*)d_out;

    k_wconv<<<256, 256>>>(Wq, Wk, Wv, Wp);
    k_ln_gather<<<NWIN, 256>>>(inpt, perm_n, perm_t, ln_g, ln_b);
    k_qkv<<<dim3(6, 1024), 256>>>(bq, bk, bv);
    k_attn<<<NWIN * 8, 128>>>();
    k_proj<<<dim3(2, 1024), 256>>>(inpt, perm_n, perm_t, bp, out);
}